// round 13
// baseline (speedup 1.0000x reference)
#include <cuda_runtime.h>

// S4D diagonal SSM scan — two-kernel chunk-parallel version, real-only xs.
// B=4, D=128, N=64 complex states, L=1024.
// out = [ all_xs real parts (b,t,d,n): B*L*D*N | ys_real (b,d,t): B*D*L ].
// Conjugate symmetry (exact): x[n+32]=conj(x[n]) => row[i]=xr[i%32];
// y_t = sum_{n<32} 2*Cr_n*xr_n.
//
// Kernel 1 (seed): one block (512 thr, 16 warps) per (b,d); warp c does a
//   4-step-blocked zero-seeded scan of chunk [64c,64c+64) -> end state; then
//   combines with dA^64 and writes per-chunk seeds to scratch.
// Kernel 2 (emit): one warp per (b,d,chunk), 1024 blocks x 8 warps -> fine
//   load balance (7v6 blocks/SM vs 4v3 for the fused kernel); seeded 64-step
//   scan emitting xs rows (one STG.64/lane, shfl-gathered) + y.

#define Dd 128
#define Nn 64
#define Bb 4
#define Ll 1024
#define CH 16
#define T0 64

__device__ float2 g_seed[Bb * Dd * CH * 32];

// ---- shared discretization helper (state n = lane) ----
__device__ __forceinline__ void discretize(
    int d, int lane,
    const float* __restrict__ log_dt, const float* __restrict__ log_A_real,
    const float* __restrict__ A_imag, const float* __restrict__ B_re,
    const float* __restrict__ B_im,
    float& dAr, float& dAi, float& dBr, float& dBi)
{
    const float dt  = __expf(log_dt[d]);
    const float Are = -__expf(log_A_real[d * 32 + lane]);
    const float Aim = A_imag[d * 32 + lane];
    const float hr = 0.5f * dt * Are;
    const float hi = 0.5f * dt * Aim;
    const float den_r = 1.0f - hr;
    const float den_i = -hi;
    const float inv = 1.0f / (den_r * den_r + den_i * den_i);
    const float num_r = 1.0f + hr;
    dAr = (num_r * den_r + hi * den_i) * inv;
    dAi = (hi * den_r - num_r * den_i) * inv;
    const float tr = dt * B_re[d * 64 + lane];
    const float ti = dt * B_im[d * 64 + lane];
    dBr = (tr * den_r + ti * den_i) * inv;
    dBi = (ti * den_r - tr * den_i) * inv;
}

// ---------------- Kernel 1: chunk end-states + seeds ----------------
__global__ __launch_bounds__(512, 4) void s4d_seed_kernel(
    const float* __restrict__ us, const float* __restrict__ log_dt,
    const float* __restrict__ log_A_real, const float* __restrict__ A_imag,
    const float* __restrict__ B_re, const float* __restrict__ B_im)
{
    __shared__ float2 ends[CH][32];

    const int lane = threadIdx.x & 31;
    const int c    = threadIdx.x >> 5;          // chunk / warp id, 0..15
    const int d    = blockIdx.x & (Dd - 1);

    float dAr, dAi, dBr, dBi;
    discretize(d, lane, log_dt, log_A_real, A_imag, B_re, B_im,
               dAr, dAi, dBr, dBi);

    // blocked coefficients: x <- dA^4 x + sum_k dA^(4-k) dB u_k
    const float dA2r = dAr * dAr - dAi * dAi;
    const float dA2i = 2.0f * dAr * dAi;
    const float dA4r = dA2r * dA2r - dA2i * dA2i;
    const float dA4i = 2.0f * dA2r * dA2i;
    const float g3r = dAr * dBr - dAi * dBi;
    const float g3i = dAr * dBi + dAi * dBr;
    const float g2r = dA2r * dBr - dA2i * dBi;
    const float g2i = dA2r * dBi + dA2i * dBr;
    const float g1r = dA2r * g3r - dA2i * g3i;
    const float g1i = dA2r * g3i + dA2i * g3r;

    const float* u = us + (size_t)blockIdx.x * Ll + c * T0;

    float xr = 0.f, xi = 0.f;
#pragma unroll
    for (int h = 0; h < 2; ++h) {
        const float uc = u[h * 32 + lane];
#pragma unroll
        for (int j = 0; j < 8; ++j) {
            const float u1 = __shfl_sync(0xffffffffu, uc, 4 * j);
            const float u2 = __shfl_sync(0xffffffffu, uc, 4 * j + 1);
            const float u3 = __shfl_sync(0xffffffffu, uc, 4 * j + 2);
            const float u4 = __shfl_sync(0xffffffffu, uc, 4 * j + 3);
            const float injr = fmaf(g1r, u1, fmaf(g2r, u2, fmaf(g3r, u3, dBr * u4)));
            const float inji = fmaf(g1i, u1, fmaf(g2i, u2, fmaf(g3i, u3, dBi * u4)));
            const float nr = fmaf(dA4r, xr, fmaf(-dA4i, xi, injr));
            const float ni = fmaf(dA4r, xi, fmaf( dA4i, xr, inji));
            xr = nr; xi = ni;
        }
    }
    ends[c][lane] = make_float2(xr, xi);
    __syncthreads();

    // combine: init_c = sum_{j<c} (dA^64)^(c-1-j) * e_j ; write seed
    float pr = dA4r, pi = dA4i;                 // dA^64 via 4 squarings
#pragma unroll
    for (int q = 0; q < 4; ++q) {
        const float sr = pr * pr - pi * pi;
        const float si = 2.0f * pr * pi;
        pr = sr; pi = si;
    }
    xr = 0.f; xi = 0.f;
    for (int j = 0; j < c; ++j) {
        const float2 e = ends[j][lane];
        const float nr = fmaf(pr, xr, fmaf(-pi, xi, e.x));
        const float ni = fmaf(pr, xi, fmaf( pi, xr, e.y));
        xr = nr; xi = ni;
    }
    g_seed[((size_t)blockIdx.x * CH + c) * 32 + lane] = make_float2(xr, xi);
}

// ---------------- Kernel 2: seeded scan, emit xs + y ----------------
__global__ __launch_bounds__(256, 8) void s4d_emit_kernel(
    const float* __restrict__ us, const float* __restrict__ log_dt,
    const float* __restrict__ log_A_real, const float* __restrict__ A_imag,
    const float* __restrict__ B_re, const float* __restrict__ B_im,
    const float* __restrict__ C_re,
    float* __restrict__ out,
    size_t xs_floats, size_t out_floats)
{
    __shared__ float ybuf[8][32 * 17];

    const int lane = threadIdx.x & 31;
    const int wib  = threadIdx.x >> 5;          // warp in block, 0..7
    const int w    = blockIdx.x * 8 + wib;      // 0 .. B*D*CH-1
    const int c    = w & (CH - 1);
    const int bd   = w >> 4;                    // (b*D + d)
    const int d    = bd & (Dd - 1);
    const int b    = bd >> 7;

    float dAr, dAi, dBr, dBi;
    discretize(d, lane, log_dt, log_A_real, A_imag, B_re, B_im,
               dAr, dAi, dBr, dBi);
    const float Cr2 = 2.0f * C_re[d * 32 + lane];

    const float2 seed = g_seed[(size_t)w * 32 + lane];
    float xr = seed.x, xi = seed.y;

    const bool xs_ok = (xs_floats >= (size_t)Bb * Ll * Dd * Nn);
    const bool y_ok  = (out_floats >= xs_floats + (size_t)Bb * Dd * Ll);

    const float* u = us + (size_t)bd * Ll + c * T0;
    float2* __restrict__ xrow2 = reinterpret_cast<float2*>(
        out + ((size_t)(b * Ll + c * T0) * Dd + d) * (size_t)Nn);
    float* __restrict__ y_out = out + xs_floats + (size_t)bd * Ll + c * T0;
    float* yb = ybuf[wib];

    const int src0 = (2 * lane) & 31;           // row-gather sources
    const int src1 = (2 * lane + 1) & 31;

#pragma unroll
    for (int t0 = 0; t0 < T0; t0 += 32) {
        const float uc = u[t0 + lane];
#pragma unroll
        for (int sg = 0; sg < 32; sg += 16) {
#pragma unroll
            for (int s = 0; s < 16; ++s) {
                const int st = sg + s;
                const float ut = __shfl_sync(0xffffffffu, uc, st);
                const float nr = fmaf(dAr, xr, fmaf(-dAi, xi, dBr * ut));
                const float ni = fmaf(dAr, xi, fmaf( dAi, xr, dBi * ut));
                xr = nr; xi = ni;

                // whole 64-float row as 32 float2 (conjugate halves equal)
                const float v0 = __shfl_sync(0xffffffffu, xr, src0);
                const float v1 = __shfl_sync(0xffffffffu, xr, src1);
                if (xs_ok)
                    xrow2[(size_t)(t0 + st) * (Dd * Nn / 2) + lane] =
                        make_float2(v0, v1);

                yb[lane * 17 + s] = Cr2 * xr;
            }
            __syncwarp();
            float acc = 0.f;
            const int col = lane & 15;
            const int hb  = lane & 16;
#pragma unroll
            for (int i = 0; i < 16; ++i)
                acc += yb[(hb + i) * 17 + col];
            acc += __shfl_xor_sync(0xffffffffu, acc, 16);
            if (y_ok && lane < 16)
                y_out[t0 + sg + lane] = acc;
            __syncwarp();
        }
    }
}

extern "C" void kernel_launch(void* const* d_in, const int* in_sizes, int n_in,
                              void* d_out, int out_size)
{
    (void)in_sizes; (void)n_in;
    const float* us         = (const float*)d_in[0];
    const float* log_dt     = (const float*)d_in[1];
    const float* log_A_real = (const float*)d_in[2];
    const float* A_imag     = (const float*)d_in[3];
    const float* B_re       = (const float*)d_in[4];
    const float* B_im       = (const float*)d_in[5];
    const float* C_re       = (const float*)d_in[6];
    float* out = (float*)d_out;

    const size_t out_floats = (size_t)out_size;
    const size_t ys_floats  = (size_t)Bb * Dd * Ll;
    const size_t xs_floats  = (out_floats > ys_floats) ? (out_floats - ys_floats) : 0;

    s4d_seed_kernel<<<Bb * Dd, 512>>>(us, log_dt, log_A_real, A_imag,
                                      B_re, B_im);
    s4d_emit_kernel<<<(Bb * Dd * CH) / 8, 256>>>(us, log_dt, log_A_real,
                                                 A_imag, B_re, B_im, C_re,
                                                 out, xs_floats, out_floats);
}